// round 2
// baseline (speedup 1.0000x reference)
#include <cuda_runtime.h>

#define NN   50000
#define NE   600000
#define IND  512
#define HID  128
#define OUTD 64
#define EPSV 0.1f

// ---------------- device scratch (no allocations allowed) ----------------
__device__ float g_h   [NN * HID];
__device__ float g_h2  [NN * HID];
__device__ float g_raw [NN * HID];
__device__ float g_dinv[NN];
__device__ int   g_deg [NN];
__device__ int   g_rowptr[NN + 1];
__device__ int   g_cursor[NN];
__device__ int2  g_csr [NE];     // (src, eid) in CSR-by-dst order
__device__ float g_norm[NE];
__device__ float g_coef[NE];
__device__ float g_al  [NN];
__device__ float g_ar  [NN];

// ---------------- graph preprocessing ----------------
__global__ void init_deg_kernel() {
    int i = blockIdx.x * blockDim.x + threadIdx.x;
    if (i < NN) g_deg[i] = 0;
}

__global__ void count_deg_kernel(const int* __restrict__ dst) {
    int e = blockIdx.x * blockDim.x + threadIdx.x;
    if (e < NE) atomicAdd(&g_deg[dst[e]], 1);
}

__global__ void dinv_kernel() {
    int i = blockIdx.x * blockDim.x + threadIdx.x;
    if (i < NN) {
        int d = g_deg[i];
        g_dinv[i] = (d > 0) ? rsqrtf((float)d) : 0.0f;
    }
}

// single-block exclusive scan of g_deg -> g_rowptr (+ cursor copy)
__global__ void scan_kernel() {
    __shared__ int sums[1024];
    const int tid = threadIdx.x;
    const int chunk = (NN + 1023) / 1024;  // 49
    int b = tid * chunk;
    int e = b + chunk; if (e > NN) e = NN;
    if (b > NN) b = NN;
    int s = 0;
    for (int i = b; i < e; i++) s += g_deg[i];
    sums[tid] = s;
    __syncthreads();
    // Hillis-Steele inclusive scan
    for (int off = 1; off < 1024; off <<= 1) {
        int v = 0;
        if (tid >= off) v = sums[tid - off];
        __syncthreads();
        if (tid >= off) sums[tid] += v;
        __syncthreads();
    }
    int prefix = (tid == 0) ? 0 : sums[tid - 1];
    for (int i = b; i < e; i++) {
        g_rowptr[i] = prefix;
        g_cursor[i] = prefix;
        prefix += g_deg[i];
    }
    if (tid == 1023) g_rowptr[NN] = sums[1023];
}

__global__ void fill_csr_kernel(const int* __restrict__ src, const int* __restrict__ dst) {
    int e = blockIdx.x * blockDim.x + threadIdx.x;
    if (e < NE) {
        int s = src[e], d = dst[e];
        g_norm[e] = g_dinv[s] * g_dinv[d];
        int p = atomicAdd(&g_cursor[d], 1);
        g_csr[p] = make_int2(s, e);
    }
}

// ---------------- GEMM1: h = relu(X @ W1^T + b1), also raw = h ----------------
// X [NN,512], W1 [128,512] row-major. BM=128, BN=128(=HID), BK=16, 256 thr, 8x8/thr.
__global__ __launch_bounds__(256) void gemm1_kernel(const float* __restrict__ X,
                                                    const float* __restrict__ W,
                                                    const float* __restrict__ bias) {
    __shared__ float Xs[16][128];
    __shared__ float Ws[16][128];
    const int tid = threadIdx.x;
    const int m0 = blockIdx.x * 128;
    const int tx = tid & 15;   // output col group (h)
    const int ty = tid >> 4;   // output row group (n)

    float acc[8][8];
#pragma unroll
    for (int i = 0; i < 8; i++)
#pragma unroll
        for (int j = 0; j < 8; j++) acc[i][j] = 0.0f;

    for (int k0 = 0; k0 < IND; k0 += 16) {
#pragma unroll
        for (int r = 0; r < 2; r++) {
            int q = tid + r * 256;     // 0..511 quads
            int row = q >> 2;
            int qc  = q & 3;
            int gr = m0 + row;
            float4 v = make_float4(0.f, 0.f, 0.f, 0.f);
            if (gr < NN) v = *(const float4*)(X + (size_t)gr * IND + k0 + qc * 4);
            Xs[qc * 4 + 0][row] = v.x;
            Xs[qc * 4 + 1][row] = v.y;
            Xs[qc * 4 + 2][row] = v.z;
            Xs[qc * 4 + 3][row] = v.w;
        }
#pragma unroll
        for (int r = 0; r < 2; r++) {
            int q = tid + r * 256;
            int row = q >> 2;          // h index 0..127
            int qc  = q & 3;
            float4 v = *(const float4*)(W + (size_t)row * IND + k0 + qc * 4);
            Ws[qc * 4 + 0][row] = v.x;
            Ws[qc * 4 + 1][row] = v.y;
            Ws[qc * 4 + 2][row] = v.z;
            Ws[qc * 4 + 3][row] = v.w;
        }
        __syncthreads();
#pragma unroll
        for (int k = 0; k < 16; k++) {
            float4 a0 = *(const float4*)&Xs[k][ty * 8];
            float4 a1 = *(const float4*)&Xs[k][ty * 8 + 4];
            float4 b0 = *(const float4*)&Ws[k][tx * 8];
            float4 b1 = *(const float4*)&Ws[k][tx * 8 + 4];
            float a[8] = {a0.x, a0.y, a0.z, a0.w, a1.x, a1.y, a1.z, a1.w};
            float b[8] = {b0.x, b0.y, b0.z, b0.w, b1.x, b1.y, b1.z, b1.w};
#pragma unroll
            for (int i = 0; i < 8; i++)
#pragma unroll
                for (int j = 0; j < 8; j++)
                    acc[i][j] = fmaf(a[i], b[j], acc[i][j]);
        }
        __syncthreads();
    }

#pragma unroll
    for (int i = 0; i < 8; i++) {
        int gr = m0 + ty * 8 + i;
        if (gr < NN) {
#pragma unroll
            for (int jv = 0; jv < 2; jv++) {
                int c = tx * 8 + jv * 4;
                float4 o;
                o.x = fmaxf(acc[i][jv * 4 + 0] + bias[c + 0], 0.f);
                o.y = fmaxf(acc[i][jv * 4 + 1] + bias[c + 1], 0.f);
                o.z = fmaxf(acc[i][jv * 4 + 2] + bias[c + 2], 0.f);
                o.w = fmaxf(acc[i][jv * 4 + 3] + bias[c + 3], 0.f);
                *(float4*)(g_h   + (size_t)gr * HID + c) = o;
                *(float4*)(g_raw + (size_t)gr * HID + c) = o;
            }
        }
    }
}

// ---------------- per-layer: al/ar GEMV (warp per node) ----------------
__global__ void dots_kernel(const float* __restrict__ att_l, const float* __restrict__ att_r,
                            int layer, int in_is_h2) {
    const float* __restrict__ hin = in_is_h2 ? g_h2 : g_h;
    int node = (blockIdx.x * blockDim.x + threadIdx.x) >> 5;
    int lane = threadIdx.x & 31;
    if (node >= NN) return;
    float4 hv = *(const float4*)(hin + (size_t)node * HID + lane * 4);
    float4 lv = *(const float4*)(att_l + layer * HID + lane * 4);
    float4 rv = *(const float4*)(att_r + layer * HID + lane * 4);
    float sl = hv.x * lv.x + hv.y * lv.y + hv.z * lv.z + hv.w * lv.w;
    float sr = hv.x * rv.x + hv.y * rv.y + hv.z * rv.z + hv.w * rv.w;
#pragma unroll
    for (int off = 16; off; off >>= 1) {
        sl += __shfl_xor_sync(0xffffffffu, sl, off);
        sr += __shfl_xor_sync(0xffffffffu, sr, off);
    }
    if (lane == 0) { g_al[node] = sl; g_ar[node] = sr; }
}

// ---------------- per-layer: edge coefficient ----------------
__global__ void coef_kernel(const int* __restrict__ src, const int* __restrict__ dst) {
    int e = blockIdx.x * blockDim.x + threadIdx.x;
    if (e < NE)
        g_coef[e] = tanhf(g_al[src[e]] + g_ar[dst[e]]) * g_norm[e];
}

// ---------------- per-layer: gather-aggregate (warp per dst node) ----------------
__global__ void agg_kernel(int in_is_h2) {
    const float* __restrict__ hin  = in_is_h2 ? g_h2 : g_h;
    float* __restrict__       hout = in_is_h2 ? g_h  : g_h2;
    int node = (blockIdx.x * blockDim.x + threadIdx.x) >> 5;
    int lane = threadIdx.x & 31;
    if (node >= NN) return;
    int b = g_rowptr[node], e = g_rowptr[node + 1];
    float4 acc = make_float4(0.f, 0.f, 0.f, 0.f);
    for (int p = b; p < e; p++) {
        int2 se = g_csr[p];
        float c = g_coef[se.y];
        float4 hv = *(const float4*)(hin + (size_t)se.x * HID + lane * 4);
        acc.x = fmaf(c, hv.x, acc.x);
        acc.y = fmaf(c, hv.y, acc.y);
        acc.z = fmaf(c, hv.z, acc.z);
        acc.w = fmaf(c, hv.w, acc.w);
    }
    float4 rv = *(const float4*)(g_raw + (size_t)node * HID + lane * 4);
    acc.x += EPSV * rv.x;
    acc.y += EPSV * rv.y;
    acc.z += EPSV * rv.z;
    acc.w += EPSV * rv.w;
    *(float4*)(hout + (size_t)node * HID + lane * 4) = acc;
}

// ---------------- GEMM2 + bias + log_softmax (warp per node) ----------------
__global__ __launch_bounds__(256) void gemm2_kernel(const float* __restrict__ W2,
                                                    const float* __restrict__ b2,
                                                    float* __restrict__ out, int write_emb) {
    __shared__ float W2t[HID * OUTD];  // [k][j], 32 KB
    for (int idx = threadIdx.x; idx < HID * OUTD; idx += 256) {
        int k = idx >> 6, j = idx & 63;
        W2t[idx] = W2[(size_t)j * HID + k];
    }
    __syncthreads();
    int lane = threadIdx.x & 31;
    int wib  = threadIdx.x >> 5;
    for (int node = blockIdx.x * 8 + wib; node < NN; node += gridDim.x * 8) {
        float4 hv = *(const float4*)(g_h2 + (size_t)node * HID + lane * 4);
        float hreg[4] = {hv.x, hv.y, hv.z, hv.w};
        float acc0 = 0.f, acc1 = 0.f;
#pragma unroll
        for (int k = 0; k < HID; k++) {
            float hk = __shfl_sync(0xffffffffu, hreg[k & 3], k >> 2);
            acc0 = fmaf(hk, W2t[k * OUTD + lane], acc0);
            acc1 = fmaf(hk, W2t[k * OUTD + 32 + lane], acc1);
        }
        float v0 = acc0 + b2[lane];
        float v1 = acc1 + b2[lane + 32];
        float m = fmaxf(v0, v1);
#pragma unroll
        for (int off = 16; off; off >>= 1) m = fmaxf(m, __shfl_xor_sync(0xffffffffu, m, off));
        float s = expf(v0 - m) + expf(v1 - m);
#pragma unroll
        for (int off = 16; off; off >>= 1) s += __shfl_xor_sync(0xffffffffu, s, off);
        float l = m + logf(s);
        out[(size_t)node * OUTD + lane]      = v0 - l;
        out[(size_t)node * OUTD + lane + 32] = v1 - l;
        if (write_emb) {
            out[(size_t)NN * OUTD + (size_t)node * OUTD + lane]      = v0;
            out[(size_t)NN * OUTD + (size_t)node * OUTD + lane + 32] = v1;
        }
    }
}

// ---------------- launch ----------------
extern "C" void kernel_launch(void* const* d_in, const int* in_sizes, int n_in,
                              void* d_out, int out_size) {
    const float* x    = (const float*)d_in[0];
    const int*   ei   = (const int*)  d_in[1];
    const float* t1w  = (const float*)d_in[2];
    const float* t1b  = (const float*)d_in[3];
    const float* t2w  = (const float*)d_in[4];
    const float* t2b  = (const float*)d_in[5];
    const float* attl = (const float*)d_in[6];
    const float* attr = (const float*)d_in[7];
    const int* src = ei;
    const int* dst = ei + NE;
    float* out = (float*)d_out;
    int write_emb = (out_size >= 2 * NN * OUTD) ? 1 : 0;

    init_deg_kernel<<<(NN + 255) / 256, 256>>>();
    count_deg_kernel<<<(NE + 255) / 256, 256>>>(dst);
    dinv_kernel<<<(NN + 255) / 256, 256>>>();
    scan_kernel<<<1, 1024>>>();
    fill_csr_kernel<<<(NE + 255) / 256, 256>>>(src, dst);

    gemm1_kernel<<<(NN + 127) / 128, 256>>>(x, t1w, t1b);

    for (int l = 0; l < 3; l++) {
        int in_is_h2 = l & 1;  // l0: h->h2, l1: h2->h, l2: h->h2
        dots_kernel<<<(NN * 32 + 255) / 256, 256>>>(attl, attr, l, in_is_h2);
        coef_kernel<<<(NE + 255) / 256, 256>>>(src, dst);
        agg_kernel<<<(NN * 32 + 255) / 256, 256>>>(in_is_h2);
    }

    gemm2_kernel<<<1184, 256>>>(t2w, t2b, out, write_emb);
}

// round 4
// speedup vs baseline: 1.3008x; 1.3008x over previous
#include <cuda_runtime.h>
#include <cuda_bf16.h>
#include <cstdint>

#define NN   50000
#define NE   600000
#define IND  512
#define HID  128
#define OUTD 64
#define EPSV 0.1f

#define SB   256
#define NB   ((NN + SB - 1) / SB)   // 196

// ---------------- device scratch (no allocations allowed) ----------------
__device__ float g_h   [NN * HID];
__device__ float g_h2  [NN * HID];
__device__ float g_raw [NN * HID];
__device__ float g_dinv[NN];
__device__ int   g_deg [NN];
__device__ int   g_rowptr[NN + 1];
__device__ int   g_cursor[NN];
__device__ int2  g_csr [NE];        // (src, __float_as_int(norm)) CSR-by-dst
__device__ float g_albuf[2][NN];
__device__ float g_arbuf[2][NN];
__device__ int   g_bsum[NB];
__device__ int   g_boff[NB];

// ---------------- graph preprocessing ----------------
__global__ void init_deg_kernel() {
    int i = blockIdx.x * blockDim.x + threadIdx.x;
    if (i < NN) g_deg[i] = 0;
}

__global__ void count_deg_kernel(const int* __restrict__ dst) {
    int e = blockIdx.x * blockDim.x + threadIdx.x;
    if (e < NE) atomicAdd(&g_deg[dst[e]], 1);
}

__global__ void dinv_kernel() {
    int i = blockIdx.x * blockDim.x + threadIdx.x;
    if (i < NN) {
        int d = g_deg[i];
        g_dinv[i] = (d > 0) ? rsqrtf((float)d) : 0.0f;
    }
}

// multi-block scan, stage 1: per-block sums
__global__ void scan_partial_kernel() {
    __shared__ int sh[SB];
    int i = blockIdx.x * SB + threadIdx.x;
    int v = (i < NN) ? g_deg[i] : 0;
    sh[threadIdx.x] = v;
    __syncthreads();
#pragma unroll
    for (int o = SB / 2; o; o >>= 1) {
        if (threadIdx.x < o) sh[threadIdx.x] += sh[threadIdx.x + o];
        __syncthreads();
    }
    if (threadIdx.x == 0) g_bsum[blockIdx.x] = sh[0];
}

// stage 2: scan block sums (1 block)
__global__ void scan_bsums_kernel() {
    __shared__ int sh[256];
    int t = threadIdx.x;
    int v = (t < NB) ? g_bsum[t] : 0;
    sh[t] = v;
    __syncthreads();
#pragma unroll
    for (int o = 1; o < 256; o <<= 1) {
        int add = (t >= o) ? sh[t - o] : 0;
        __syncthreads();
        sh[t] += add;
        __syncthreads();
    }
    if (t < NB) g_boff[t] = sh[t] - v;   // exclusive
    if (t == 255) g_rowptr[NN] = sh[255];
}

// stage 3: expand to per-element exclusive scan
__global__ void scan_expand_kernel() {
    __shared__ int sh[SB];
    int i = blockIdx.x * SB + threadIdx.x;
    int v = (i < NN) ? g_deg[i] : 0;
    sh[threadIdx.x] = v;
    __syncthreads();
#pragma unroll
    for (int o = 1; o < SB; o <<= 1) {
        int add = (threadIdx.x >= o) ? sh[threadIdx.x - o] : 0;
        __syncthreads();
        sh[threadIdx.x] += add;
        __syncthreads();
    }
    if (i < NN) {
        int excl = g_boff[blockIdx.x] + sh[threadIdx.x] - v;
        g_rowptr[i] = excl;
        g_cursor[i] = excl;
    }
}

__global__ void fill_csr_kernel(const int* __restrict__ src, const int* __restrict__ dst) {
    int e = blockIdx.x * blockDim.x + threadIdx.x;
    if (e < NE) {
        int s = src[e], d = dst[e];
        float nrm = g_dinv[s] * g_dinv[d];
        int p = atomicAdd(&g_cursor[d], 1);
        g_csr[p] = make_int2(s, __float_as_int(nrm));
    }
}

// ---------------- GEMM1: h = relu(X @ W1^T + b1) via bf16-split mma.sync ----
// C = Ah*Bh + Ah*Bl + Al*Bh  (fp32 accum; residual ~1e-5 rel)
// Block tile 128x128, K chunks of 32. 256 threads = 8 warps (4 in M, 2 in N).
#define KC 32
#define KP 36   // padded k extent (bf16 elems) -> 18 words, conflict-free

__device__ __forceinline__ uint32_t ldsm32(const __nv_bfloat16* base, int row, int k) {
    return *(const uint32_t*)(base + row * KP + k);
}

__device__ __forceinline__ void mma16816(float* d, const uint32_t* a, uint32_t b0, uint32_t b1) {
    asm volatile(
        "mma.sync.aligned.m16n8k16.row.col.f32.bf16.bf16.f32 "
        "{%0,%1,%2,%3}, {%4,%5,%6,%7}, {%8,%9}, {%0,%1,%2,%3};"
        : "+f"(d[0]), "+f"(d[1]), "+f"(d[2]), "+f"(d[3])
        : "r"(a[0]), "r"(a[1]), "r"(a[2]), "r"(a[3]), "r"(b0), "r"(b1));
}

__global__ __launch_bounds__(256) void gemm1_kernel(const float* __restrict__ X,
                                                    const float* __restrict__ W,
                                                    const float* __restrict__ bias) {
    __shared__ __nv_bfloat16 Ah[128 * KP];
    __shared__ __nv_bfloat16 Al[128 * KP];
    __shared__ __nv_bfloat16 Bh[128 * KP];
    __shared__ __nv_bfloat16 Bl[128 * KP];

    const int tid  = threadIdx.x;
    const int m0   = blockIdx.x * 128;
    const int lane = tid & 31;
    const int wid  = tid >> 5;
    const int wm   = wid & 3;          // M direction (4 warps)
    const int wn   = wid >> 2;         // N direction (2 warps)
    const int wmB  = wm * 32;
    const int wnB  = wn * 64;
    const int r    = lane >> 2;
    const int c2   = (lane & 3) * 2;

    float acc[2][8][4];
#pragma unroll
    for (int mi = 0; mi < 2; mi++)
#pragma unroll
        for (int ni = 0; ni < 8; ni++)
#pragma unroll
            for (int j = 0; j < 4; j++) acc[mi][ni][j] = 0.0f;

    for (int k0 = 0; k0 < IND; k0 += KC) {
        // global -> reg
        float4 xa[4], wb[4];
#pragma unroll
        for (int rr = 0; rr < 4; rr++) {
            int q   = tid + rr * 256;      // 0..1023
            int row = q >> 3;              // 0..127
            int kq  = (q & 7) * 4;
            int gr  = m0 + row;
            float4 v = make_float4(0.f, 0.f, 0.f, 0.f);
            if (gr < NN) v = *(const float4*)(X + (size_t)gr * IND + k0 + kq);
            xa[rr] = v;
            wb[rr] = *(const float4*)(W + (size_t)row * IND + k0 + kq);
        }
        __syncthreads();   // previous compute done
#pragma unroll
        for (int rr = 0; rr < 4; rr++) {
            int q   = tid + rr * 256;
            int row = q >> 3;
            int kq  = (q & 7) * 4;
            float f[4] = {xa[rr].x, xa[rr].y, xa[rr].z, xa[rr].w};
            float g[4] = {wb[rr].x, wb[rr].y, wb[rr].z, wb[rr].w};
#pragma unroll
            for (int j = 0; j < 4; j++) {
                __nv_bfloat16 h = __float2bfloat16(f[j]);
                Ah[row * KP + kq + j] = h;
                Al[row * KP + kq + j] = __float2bfloat16(f[j] - __bfloat162float(h));
                __nv_bfloat16 hw = __float2bfloat16(g[j]);
                Bh[row * KP + kq + j] = hw;
                Bl[row * KP + kq + j] = __float2bfloat16(g[j] - __bfloat162float(hw));
            }
        }
        __syncthreads();

#pragma unroll
        for (int s = 0; s < 2; s++) {
            const int kb = s * 16;
            uint32_t ah[2][4], alo[2][4];
#pragma unroll
            for (int mi = 0; mi < 2; mi++) {
                int row0 = wmB + mi * 16 + r;
                ah[mi][0]  = ldsm32(Ah, row0,     kb + c2);
                ah[mi][1]  = ldsm32(Ah, row0 + 8, kb + c2);
                ah[mi][2]  = ldsm32(Ah, row0,     kb + c2 + 8);
                ah[mi][3]  = ldsm32(Ah, row0 + 8, kb + c2 + 8);
                alo[mi][0] = ldsm32(Al, row0,     kb + c2);
                alo[mi][1] = ldsm32(Al, row0 + 8, kb + c2);
                alo[mi][2] = ldsm32(Al, row0,     kb + c2 + 8);
                alo[mi][3] = ldsm32(Al, row0 + 8, kb + c2 + 8);
            }
#pragma unroll
            for (int ni = 0; ni < 8; ni++) {
                int n = wnB + ni * 8 + r;
                uint32_t bh0 = ldsm32(Bh, n, kb + c2);
                uint32_t bh1 = ldsm32(Bh, n, kb + c2 + 8);
                uint32_t bl0 = ldsm32(Bl, n, kb + c2);
                uint32_t bl1 = ldsm32(Bl, n, kb + c2 + 8);
#pragma unroll
                for (int mi = 0; mi < 2; mi++) {
                    mma16816(acc[mi][ni], ah[mi],  bh0, bh1);
                    mma16816(acc[mi][ni], ah[mi],  bl0, bl1);
                    mma16816(acc[mi][ni], alo[mi], bh0, bh1);
                }
            }
        }
    }

    // epilogue: bias + relu, write g_h and g_raw
#pragma unroll
    for (int mi = 0; mi < 2; mi++) {
        int row_a = wmB + mi * 16 + r;
        int gr0 = m0 + row_a;
        int gr1 = gr0 + 8;
#pragma unroll
        for (int ni = 0; ni < 8; ni++) {
            int col = wnB + ni * 8 + c2;
            float2 bb = *(const float2*)(bias + col);
            float2 o0, o1;
            o0.x = fmaxf(acc[mi][ni][0] + bb.x, 0.f);
            o0.y = fmaxf(acc[mi][ni][1] + bb.y, 0.f);
            o1.x = fmaxf(acc[mi][ni][2] + bb.x, 0.f);
            o1.y = fmaxf(acc[mi][ni][3] + bb.y, 0.f);
            if (gr0 < NN) {
                *(float2*)(g_h   + (size_t)gr0 * HID + col) = o0;
                *(float2*)(g_raw + (size_t)gr0 * HID + col) = o0;
            }
            if (gr1 < NN) {
                *(float2*)(g_h   + (size_t)gr1 * HID + col) = o1;
                *(float2*)(g_raw + (size_t)gr1 * HID + col) = o1;
            }
        }
    }
}

// ---------------- layer-0 dots: al/ar = h @ att (warp per node) -------------
__global__ void dots_kernel(const float* __restrict__ att_l, const float* __restrict__ att_r) {
    int node = (blockIdx.x * blockDim.x + threadIdx.x) >> 5;
    int lane = threadIdx.x & 31;
    if (node >= NN) return;
    float4 hv = *(const float4*)(g_h + (size_t)node * HID + lane * 4);
    float4 lv = *(const float4*)(att_l + lane * 4);
    float4 rv = *(const float4*)(att_r + lane * 4);
    float sl = hv.x * lv.x + hv.y * lv.y + hv.z * lv.z + hv.w * lv.w;
    float sr = hv.x * rv.x + hv.y * rv.y + hv.z * rv.z + hv.w * rv.w;
#pragma unroll
    for (int off = 16; off; off >>= 1) {
        sl += __shfl_xor_sync(0xffffffffu, sl, off);
        sr += __shfl_xor_sync(0xffffffffu, sr, off);
    }
    if (lane == 0) { g_albuf[0][node] = sl; g_arbuf[0][node] = sr; }
}

// ---------------- fused aggregate (+ next-layer dots) (warp per dst) --------
__global__ void agg_kernel(int l, int in_is_h2,
                           const float* __restrict__ att_l, const float* __restrict__ att_r) {
    const float* __restrict__ hin  = in_is_h2 ? g_h2 : g_h;
    float* __restrict__       hout = in_is_h2 ? g_h  : g_h2;
    const int cur = l & 1;
    const int nxt = cur ^ 1;

    int node = (blockIdx.x * blockDim.x + threadIdx.x) >> 5;
    int lane = threadIdx.x & 31;
    if (node >= NN) return;

    int b = g_rowptr[node], e = g_rowptr[node + 1];
    float ar_n = g_arbuf[cur][node];
    float4 acc = make_float4(0.f, 0.f, 0.f, 0.f);
    for (int p = b; p < e; p++) {
        int2 se = g_csr[p];
        float c = tanhf(g_albuf[cur][se.x] + ar_n) * __int_as_float(se.y);
        float4 hv = *(const float4*)(hin + (size_t)se.x * HID + lane * 4);
        acc.x = fmaf(c, hv.x, acc.x);
        acc.y = fmaf(c, hv.y, acc.y);
        acc.z = fmaf(c, hv.z, acc.z);
        acc.w = fmaf(c, hv.w, acc.w);
    }
    float4 rv = *(const float4*)(g_raw + (size_t)node * HID + lane * 4);
    acc.x += EPSV * rv.x;
    acc.y += EPSV * rv.y;
    acc.z += EPSV * rv.z;
    acc.w += EPSV * rv.w;
    *(float4*)(hout + (size_t)node * HID + lane * 4) = acc;

    if (l < 2) {  // next-layer al/ar dots
        float4 lv = *(const float4*)(att_l + (l + 1) * HID + lane * 4);
        float4 rv2 = *(const float4*)(att_r + (l + 1) * HID + lane * 4);
        float sl = acc.x * lv.x + acc.y * lv.y + acc.z * lv.z + acc.w * lv.w;
        float sr = acc.x * rv2.x + acc.y * rv2.y + acc.z * rv2.z + acc.w * rv2.w;
#pragma unroll
        for (int off = 16; off; off >>= 1) {
            sl += __shfl_xor_sync(0xffffffffu, sl, off);
            sr += __shfl_xor_sync(0xffffffffu, sr, off);
        }
        if (lane == 0) { g_albuf[nxt][node] = sl; g_arbuf[nxt][node] = sr; }
    }
}

// ---------------- GEMM2 + bias + log_softmax (warp per node) ----------------
__global__ __launch_bounds__(256) void gemm2_kernel(const float* __restrict__ W2,
                                                    const float* __restrict__ b2,
                                                    float* __restrict__ out, int write_emb) {
    __shared__ float W2t[HID * OUTD];  // [k][j], 32 KB
    for (int idx = threadIdx.x; idx < HID * OUTD; idx += 256) {
        int k = idx >> 6, j = idx & 63;
        W2t[idx] = W2[(size_t)j * HID + k];
    }
    __syncthreads();
    int lane = threadIdx.x & 31;
    int wib  = threadIdx.x >> 5;
    for (int node = blockIdx.x * 8 + wib; node < NN; node += gridDim.x * 8) {
        float4 hv = *(const float4*)(g_h2 + (size_t)node * HID + lane * 4);
        float hreg[4] = {hv.x, hv.y, hv.z, hv.w};
        float acc0 = 0.f, acc1 = 0.f;
#pragma unroll
        for (int k = 0; k < HID; k++) {
            float hk = __shfl_sync(0xffffffffu, hreg[k & 3], k >> 2);
            acc0 = fmaf(hk, W2t[k * OUTD + lane], acc0);
            acc1 = fmaf(hk, W2t[k * OUTD + 32 + lane], acc1);
        }
        float v0 = acc0 + b2[lane];
        float v1 = acc1 + b2[lane + 32];
        float m = fmaxf(v0, v1);
#pragma unroll
        for (int off = 16; off; off >>= 1) m = fmaxf(m, __shfl_xor_sync(0xffffffffu, m, off));
        float s = expf(v0 - m) + expf(v1 - m);
#pragma unroll
        for (int off = 16; off; off >>= 1) s += __shfl_xor_sync(0xffffffffu, s, off);
        float lgt = m + logf(s);
        out[(size_t)node * OUTD + lane]      = v0 - lgt;
        out[(size_t)node * OUTD + lane + 32] = v1 - lgt;
        if (write_emb) {
            out[(size_t)NN * OUTD + (size_t)node * OUTD + lane]      = v0;
            out[(size_t)NN * OUTD + (size_t)node * OUTD + lane + 32] = v1;
        }
    }
}

// ---------------- launch ----------------
extern "C" void kernel_launch(void* const* d_in, const int* in_sizes, int n_in,
                              void* d_out, int out_size) {
    const float* x    = (const float*)d_in[0];
    const int*   ei   = (const int*)  d_in[1];
    const float* t1w  = (const float*)d_in[2];
    const float* t1b  = (const float*)d_in[3];
    const float* t2w  = (const float*)d_in[4];
    const float* t2b  = (const float*)d_in[5];
    const float* attl = (const float*)d_in[6];
    const float* attr = (const float*)d_in[7];
    const int* src = ei;
    const int* dst = ei + NE;
    float* out = (float*)d_out;
    int write_emb = (out_size >= 2 * NN * OUTD) ? 1 : 0;

    init_deg_kernel<<<(NN + 255) / 256, 256>>>();
    count_deg_kernel<<<(NE + 255) / 256, 256>>>(dst);
    dinv_kernel<<<(NN + 255) / 256, 256>>>();
    scan_partial_kernel<<<NB, SB>>>();
    scan_bsums_kernel<<<1, 256>>>();
    scan_expand_kernel<<<NB, SB>>>();
    fill_csr_kernel<<<(NE + 255) / 256, 256>>>(src, dst);

    gemm1_kernel<<<(NN + 127) / 128, 256>>>(x, t1w, t1b);
    dots_kernel<<<(NN * 32 + 255) / 256, 256>>>(attl, attr);

    for (int l = 0; l < 3; l++) {
        int in_is_h2 = l & 1;  // l0: h->h2, l1: h2->h, l2: h->h2
        agg_kernel<<<(NN * 32 + 255) / 256, 256>>>(l, in_is_h2, attl, attr);
    }

    gemm2_kernel<<<1184, 256>>>(t2w, t2b, out, write_emb);
}

// round 5
// speedup vs baseline: 1.3784x; 1.0596x over previous
#include <cuda_runtime.h>
#include <cuda_bf16.h>
#include <cstdint>

#define NN   50000
#define NE   600000
#define IND  512
#define HID  128
#define OUTD 64
#define EPSV 0.1f

#define SB   256
#define NB   ((NN + SB - 1) / SB)   // 196

// ---------------- device scratch (no allocations allowed) ----------------
__device__ float g_h   [NN * HID];
__device__ float g_h2  [NN * HID];
__device__ float g_raw [NN * HID];
__device__ float g_dinv[NN];
__device__ int   g_deg [NN];
__device__ int   g_rowptr[NN + 1];
__device__ int   g_cursor[NN];
__device__ int2  g_csr [NE];        // (src, __float_as_int(norm)) CSR-by-dst
__device__ float g_albuf[2][NN];
__device__ float g_arbuf[2][NN];
__device__ int   g_bsum[NB];
__device__ int   g_boff[NB];
__device__ __nv_bfloat16 g_w1h[HID * IND];
__device__ __nv_bfloat16 g_w1l[HID * IND];

// ---------------- split helper: f32 -> (bf16 hi trunc, bf16 lo rn), packed --
__device__ __forceinline__ void split2(float fx, float fy, uint32_t& hi, uint32_t& lo) {
    uint32_t ix = __float_as_uint(fx), iy = __float_as_uint(fy);
    hi = __byte_perm(ix, iy, 0x7632);                    // {hi16(x), hi16(y)}
    float hx = __uint_as_float(ix & 0xFFFF0000u);
    float hy = __uint_as_float(iy & 0xFFFF0000u);
    __nv_bfloat162 l2 = __floats2bfloat162_rn(fx - hx, fy - hy);
    lo = *(uint32_t*)&l2;
}

// ---------------- W1 preconversion (once) ----------------
__global__ void wconv_kernel(const float* __restrict__ W) {
    int i = blockIdx.x * blockDim.x + threadIdx.x;   // pairs
    if (i * 2 < HID * IND) {
        float2 v = *(const float2*)(W + i * 2);
        uint32_t h, l;
        split2(v.x, v.y, h, l);
        *(uint32_t*)(g_w1h + i * 2) = h;
        *(uint32_t*)(g_w1l + i * 2) = l;
    }
}

// ---------------- graph preprocessing ----------------
__global__ void init_deg_kernel() {
    int i = blockIdx.x * blockDim.x + threadIdx.x;
    if (i < NN) g_deg[i] = 0;
}

__global__ void count_deg_kernel(const int* __restrict__ dst) {
    int e = blockIdx.x * blockDim.x + threadIdx.x;
    if (e < NE) atomicAdd(&g_deg[dst[e]], 1);
}

// scan stage 1: per-block sums (+ fused dinv)
__global__ void scan_partial_kernel() {
    __shared__ int sh[SB];
    int i = blockIdx.x * SB + threadIdx.x;
    int v = 0;
    if (i < NN) {
        v = g_deg[i];
        g_dinv[i] = (v > 0) ? rsqrtf((float)v) : 0.0f;
    }
    sh[threadIdx.x] = v;
    __syncthreads();
#pragma unroll
    for (int o = SB / 2; o; o >>= 1) {
        if (threadIdx.x < o) sh[threadIdx.x] += sh[threadIdx.x + o];
        __syncthreads();
    }
    if (threadIdx.x == 0) g_bsum[blockIdx.x] = sh[0];
}

// stage 2: scan block sums (1 block)
__global__ void scan_bsums_kernel() {
    __shared__ int sh[256];
    int t = threadIdx.x;
    int v = (t < NB) ? g_bsum[t] : 0;
    sh[t] = v;
    __syncthreads();
#pragma unroll
    for (int o = 1; o < 256; o <<= 1) {
        int add = (t >= o) ? sh[t - o] : 0;
        __syncthreads();
        sh[t] += add;
        __syncthreads();
    }
    if (t < NB) g_boff[t] = sh[t] - v;   // exclusive
    if (t == 255) g_rowptr[NN] = sh[255];
}

// stage 3: expand to per-element exclusive scan
__global__ void scan_expand_kernel() {
    __shared__ int sh[SB];
    int i = blockIdx.x * SB + threadIdx.x;
    int v = (i < NN) ? g_deg[i] : 0;
    sh[threadIdx.x] = v;
    __syncthreads();
#pragma unroll
    for (int o = 1; o < SB; o <<= 1) {
        int add = (threadIdx.x >= o) ? sh[threadIdx.x - o] : 0;
        __syncthreads();
        sh[threadIdx.x] += add;
        __syncthreads();
    }
    if (i < NN) {
        int excl = g_boff[blockIdx.x] + sh[threadIdx.x] - v;
        g_rowptr[i] = excl;
        g_cursor[i] = excl;
    }
}

__global__ void fill_csr_kernel(const int* __restrict__ src, const int* __restrict__ dst) {
    int e = blockIdx.x * blockDim.x + threadIdx.x;
    if (e < NE) {
        int s = src[e], d = dst[e];
        float nrm = g_dinv[s] * g_dinv[d];
        int p = atomicAdd(&g_cursor[d], 1);
        g_csr[p] = make_int2(s, __float_as_int(nrm));
    }
}

// ---------------- GEMM1: h = relu(X @ W1^T + b1) via bf16-split mma.sync ----
// C = Ah*Bh + Ah*Bl + Al*Bh. Block tile 128x128, K chunks of 32, 8 warps.
#define KC 32
#define KP 40   // padded k extent in bf16 (20 words) -> conflict-free, 16B rows

__device__ __forceinline__ uint32_t ldsm32(const __nv_bfloat16* base, int row, int k) {
    return *(const uint32_t*)(base + row * KP + k);
}

__device__ __forceinline__ void mma16816(float* d, const uint32_t* a, uint32_t b0, uint32_t b1) {
    asm volatile(
        "mma.sync.aligned.m16n8k16.row.col.f32.bf16.bf16.f32 "
        "{%0,%1,%2,%3}, {%4,%5,%6,%7}, {%8,%9}, {%0,%1,%2,%3};"
        : "+f"(d[0]), "+f"(d[1]), "+f"(d[2]), "+f"(d[3])
        : "r"(a[0]), "r"(a[1]), "r"(a[2]), "r"(a[3]), "r"(b0), "r"(b1));
}

__global__ __launch_bounds__(256) void gemm1_kernel(const float* __restrict__ X,
                                                    const float* __restrict__ bias) {
    __shared__ __nv_bfloat16 Ah[128 * KP];
    __shared__ __nv_bfloat16 Al[128 * KP];
    __shared__ __nv_bfloat16 Bh[128 * KP];
    __shared__ __nv_bfloat16 Bl[128 * KP];

    const int tid  = threadIdx.x;
    const int m0   = blockIdx.x * 128;
    const int lane = tid & 31;
    const int wid  = tid >> 5;
    const int wm   = wid & 3;          // M direction (4 warps)
    const int wn   = wid >> 2;         // N direction (2 warps)
    const int wmB  = wm * 32;
    const int wnB  = wn * 64;
    const int r    = lane >> 2;
    const int c2   = (lane & 3) * 2;

    float acc[2][8][4];
#pragma unroll
    for (int mi = 0; mi < 2; mi++)
#pragma unroll
        for (int ni = 0; ni < 8; ni++)
#pragma unroll
            for (int j = 0; j < 4; j++) acc[mi][ni][j] = 0.0f;

    for (int k0 = 0; k0 < IND; k0 += KC) {
        // ---- global -> reg
        float4 xa[4];
        uint4  wh[2], wl[2];
#pragma unroll
        for (int rr = 0; rr < 4; rr++) {
            int q   = tid + rr * 256;      // 0..1023
            int row = q >> 3;              // 0..127
            int kq  = (q & 7) * 4;
            int gr  = m0 + row;
            float4 v = make_float4(0.f, 0.f, 0.f, 0.f);
            if (gr < NN) v = *(const float4*)(X + (size_t)gr * IND + k0 + kq);
            xa[rr] = v;
        }
#pragma unroll
        for (int rr = 0; rr < 2; rr++) {
            int q   = tid + rr * 256;      // 0..511
            int row = q >> 2;              // 0..127 (hid)
            int kq8 = (q & 3) * 8;
            wh[rr] = *(const uint4*)(g_w1h + (size_t)row * IND + k0 + kq8);
            wl[rr] = *(const uint4*)(g_w1l + (size_t)row * IND + k0 + kq8);
        }
        __syncthreads();   // previous compute done
        // ---- reg -> smem (split X, copy W)
#pragma unroll
        for (int rr = 0; rr < 4; rr++) {
            int q   = tid + rr * 256;
            int row = q >> 3;
            int kq  = (q & 7) * 4;
            uint32_t h0, l0, h1, l1;
            split2(xa[rr].x, xa[rr].y, h0, l0);
            split2(xa[rr].z, xa[rr].w, h1, l1);
            *(uint2*)(Ah + row * KP + kq) = make_uint2(h0, h1);
            *(uint2*)(Al + row * KP + kq) = make_uint2(l0, l1);
        }
#pragma unroll
        for (int rr = 0; rr < 2; rr++) {
            int q   = tid + rr * 256;
            int row = q >> 2;
            int kq8 = (q & 3) * 8;
            *(uint4*)(Bh + row * KP + kq8) = wh[rr];
            *(uint4*)(Bl + row * KP + kq8) = wl[rr];
        }
        __syncthreads();

#pragma unroll
        for (int s = 0; s < 2; s++) {
            const int kb = s * 16;
            uint32_t ah[2][4], alo[2][4];
#pragma unroll
            for (int mi = 0; mi < 2; mi++) {
                int row0 = wmB + mi * 16 + r;
                ah[mi][0]  = ldsm32(Ah, row0,     kb + c2);
                ah[mi][1]  = ldsm32(Ah, row0 + 8, kb + c2);
                ah[mi][2]  = ldsm32(Ah, row0,     kb + c2 + 8);
                ah[mi][3]  = ldsm32(Ah, row0 + 8, kb + c2 + 8);
                alo[mi][0] = ldsm32(Al, row0,     kb + c2);
                alo[mi][1] = ldsm32(Al, row0 + 8, kb + c2);
                alo[mi][2] = ldsm32(Al, row0,     kb + c2 + 8);
                alo[mi][3] = ldsm32(Al, row0 + 8, kb + c2 + 8);
            }
#pragma unroll
            for (int ni = 0; ni < 8; ni++) {
                int n = wnB + ni * 8 + r;
                uint32_t bh0 = ldsm32(Bh, n, kb + c2);
                uint32_t bh1 = ldsm32(Bh, n, kb + c2 + 8);
                uint32_t bl0 = ldsm32(Bl, n, kb + c2);
                uint32_t bl1 = ldsm32(Bl, n, kb + c2 + 8);
#pragma unroll
                for (int mi = 0; mi < 2; mi++) {
                    mma16816(acc[mi][ni], ah[mi],  bh0, bh1);
                    mma16816(acc[mi][ni], ah[mi],  bl0, bl1);
                    mma16816(acc[mi][ni], alo[mi], bh0, bh1);
                }
            }
        }
    }

    // epilogue: bias + relu, write g_h and g_raw
#pragma unroll
    for (int mi = 0; mi < 2; mi++) {
        int row_a = wmB + mi * 16 + r;
        int gr0 = m0 + row_a;
        int gr1 = gr0 + 8;
#pragma unroll
        for (int ni = 0; ni < 8; ni++) {
            int col = wnB + ni * 8 + c2;
            float2 bb = *(const float2*)(bias + col);
            float2 o0, o1;
            o0.x = fmaxf(acc[mi][ni][0] + bb.x, 0.f);
            o0.y = fmaxf(acc[mi][ni][1] + bb.y, 0.f);
            o1.x = fmaxf(acc[mi][ni][2] + bb.x, 0.f);
            o1.y = fmaxf(acc[mi][ni][3] + bb.y, 0.f);
            if (gr0 < NN) {
                *(float2*)(g_h   + (size_t)gr0 * HID + col) = o0;
                *(float2*)(g_raw + (size_t)gr0 * HID + col) = o0;
            }
            if (gr1 < NN) {
                *(float2*)(g_h   + (size_t)gr1 * HID + col) = o1;
                *(float2*)(g_raw + (size_t)gr1 * HID + col) = o1;
            }
        }
    }
}

// ---------------- layer-0 dots: al/ar = h @ att (warp per node) -------------
__global__ void dots_kernel(const float* __restrict__ att_l, const float* __restrict__ att_r) {
    int node = (blockIdx.x * blockDim.x + threadIdx.x) >> 5;
    int lane = threadIdx.x & 31;
    if (node >= NN) return;
    float4 hv = *(const float4*)(g_h + (size_t)node * HID + lane * 4);
    float4 lv = *(const float4*)(att_l + lane * 4);
    float4 rv = *(const float4*)(att_r + lane * 4);
    float sl = hv.x * lv.x + hv.y * lv.y + hv.z * lv.z + hv.w * lv.w;
    float sr = hv.x * rv.x + hv.y * rv.y + hv.z * rv.z + hv.w * rv.w;
#pragma unroll
    for (int off = 16; off; off >>= 1) {
        sl += __shfl_xor_sync(0xffffffffu, sl, off);
        sr += __shfl_xor_sync(0xffffffffu, sr, off);
    }
    if (lane == 0) { g_albuf[0][node] = sl; g_arbuf[0][node] = sr; }
}

// ---------------- fused aggregate (+ next-layer dots) (warp per dst) --------
__global__ void agg_kernel(int l, int in_is_h2,
                           const float* __restrict__ att_l, const float* __restrict__ att_r) {
    const float* __restrict__ hin  = in_is_h2 ? g_h2 : g_h;
    float* __restrict__       hout = in_is_h2 ? g_h  : g_h2;
    const int cur = l & 1;
    const int nxt = cur ^ 1;

    int node = (blockIdx.x * blockDim.x + threadIdx.x) >> 5;
    int lane = threadIdx.x & 31;
    if (node >= NN) return;

    int b = g_rowptr[node], e = g_rowptr[node + 1];
    float ar_n = g_arbuf[cur][node];
    float4 acc = make_float4(0.f, 0.f, 0.f, 0.f);
    int p = b;
    for (; p + 2 <= e; p += 2) {
        int2 se0 = g_csr[p];
        int2 se1 = g_csr[p + 1];
        float al0 = g_albuf[cur][se0.x];
        float al1 = g_albuf[cur][se1.x];
        float4 hv0 = *(const float4*)(hin + (size_t)se0.x * HID + lane * 4);
        float4 hv1 = *(const float4*)(hin + (size_t)se1.x * HID + lane * 4);
        float c0 = tanhf(al0 + ar_n) * __int_as_float(se0.y);
        float c1 = tanhf(al1 + ar_n) * __int_as_float(se1.y);
        acc.x = fmaf(c0, hv0.x, acc.x); acc.x = fmaf(c1, hv1.x, acc.x);
        acc.y = fmaf(c0, hv0.y, acc.y); acc.y = fmaf(c1, hv1.y, acc.y);
        acc.z = fmaf(c0, hv0.z, acc.z); acc.z = fmaf(c1, hv1.z, acc.z);
        acc.w = fmaf(c0, hv0.w, acc.w); acc.w = fmaf(c1, hv1.w, acc.w);
    }
    for (; p < e; p++) {
        int2 se = g_csr[p];
        float c = tanhf(g_albuf[cur][se.x] + ar_n) * __int_as_float(se.y);
        float4 hv = *(const float4*)(hin + (size_t)se.x * HID + lane * 4);
        acc.x = fmaf(c, hv.x, acc.x);
        acc.y = fmaf(c, hv.y, acc.y);
        acc.z = fmaf(c, hv.z, acc.z);
        acc.w = fmaf(c, hv.w, acc.w);
    }
    float4 rv = *(const float4*)(g_raw + (size_t)node * HID + lane * 4);
    acc.x += EPSV * rv.x;
    acc.y += EPSV * rv.y;
    acc.z += EPSV * rv.z;
    acc.w += EPSV * rv.w;
    *(float4*)(hout + (size_t)node * HID + lane * 4) = acc;

    if (l < 2) {  // next-layer al/ar dots
        float4 lv  = *(const float4*)(att_l + (l + 1) * HID + lane * 4);
        float4 rv2 = *(const float4*)(att_r + (l + 1) * HID + lane * 4);
        float sl = acc.x * lv.x + acc.y * lv.y + acc.z * lv.z + acc.w * lv.w;
        float sr = acc.x * rv2.x + acc.y * rv2.y + acc.z * rv2.z + acc.w * rv2.w;
#pragma unroll
        for (int off = 16; off; off >>= 1) {
            sl += __shfl_xor_sync(0xffffffffu, sl, off);
            sr += __shfl_xor_sync(0xffffffffu, sr, off);
        }
        if (lane == 0) { g_albuf[nxt][node] = sl; g_arbuf[nxt][node] = sr; }
    }
}

// ---------------- GEMM2 + bias + log_softmax (warp per node) ----------------
__global__ __launch_bounds__(256) void gemm2_kernel(const float* __restrict__ W2,
                                                    const float* __restrict__ b2,
                                                    float* __restrict__ out, int write_emb) {
    __shared__ float W2t[HID * OUTD];  // [k][j], 32 KB
    for (int idx = threadIdx.x; idx < HID * OUTD; idx += 256) {
        int k = idx >> 6, j = idx & 63;
        W2t[idx] = W2[(size_t)j * HID + k];
    }
    __syncthreads();
    int lane = threadIdx.x & 31;
    int wib  = threadIdx.x >> 5;
    for (int node = blockIdx.x * 8 + wib; node < NN; node += gridDim.x * 8) {
        float4 hv = *(const float4*)(g_h2 + (size_t)node * HID + lane * 4);
        float hreg[4] = {hv.x, hv.y, hv.z, hv.w};
        float acc0 = 0.f, acc1 = 0.f;
#pragma unroll
        for (int k = 0; k < HID; k++) {
            float hk = __shfl_sync(0xffffffffu, hreg[k & 3], k >> 2);
            acc0 = fmaf(hk, W2t[k * OUTD + lane], acc0);
            acc1 = fmaf(hk, W2t[k * OUTD + 32 + lane], acc1);
        }
        float v0 = acc0 + b2[lane];
        float v1 = acc1 + b2[lane + 32];
        float m = fmaxf(v0, v1);
#pragma unroll
        for (int off = 16; off; off >>= 1) m = fmaxf(m, __shfl_xor_sync(0xffffffffu, m, off));
        float s = expf(v0 - m) + expf(v1 - m);
#pragma unroll
        for (int off = 16; off; off >>= 1) s += __shfl_xor_sync(0xffffffffu, s, off);
        float lgt = m + logf(s);
        out[(size_t)node * OUTD + lane]      = v0 - lgt;
        out[(size_t)node * OUTD + lane + 32] = v1 - lgt;
        if (write_emb) {
            out[(size_t)NN * OUTD + (size_t)node * OUTD + lane]      = v0;
            out[(size_t)NN * OUTD + (size_t)node * OUTD + lane + 32] = v1;
        }
    }
}

// ---------------- launch ----------------
extern "C" void kernel_launch(void* const* d_in, const int* in_sizes, int n_in,
                              void* d_out, int out_size) {
    const float* x    = (const float*)d_in[0];
    const int*   ei   = (const int*)  d_in[1];
    const float* t1w  = (const float*)d_in[2];
    const float* t1b  = (const float*)d_in[3];
    const float* t2w  = (const float*)d_in[4];
    const float* t2b  = (const float*)d_in[5];
    const float* attl = (const float*)d_in[6];
    const float* attr = (const float*)d_in[7];
    const int* src = ei;
    const int* dst = ei + NE;
    float* out = (float*)d_out;
    int write_emb = (out_size >= 2 * NN * OUTD) ? 1 : 0;

    wconv_kernel<<<(HID * IND / 2 + 255) / 256, 256>>>(t1w);            // 1
    init_deg_kernel<<<(NN + 255) / 256, 256>>>();                       // 2
    count_deg_kernel<<<(NE + 255) / 256, 256>>>(dst);                   // 3
    scan_partial_kernel<<<NB, SB>>>();                                  // 4 (+dinv)
    scan_bsums_kernel<<<1, 256>>>();                                    // 5
    gemm1_kernel<<<(NN + 127) / 128, 256>>>(x, t1b);                    // 6 <- ncu target
    scan_expand_kernel<<<NB, SB>>>();                                   // 7
    fill_csr_kernel<<<(NE + 255) / 256, 256>>>(src, dst);               // 8
    dots_kernel<<<(NN * 32 + 255) / 256, 256>>>(attl, attr);            // 9

    for (int l = 0; l < 3; l++) {
        int in_is_h2 = l & 1;  // l0: h->h2, l1: h2->h, l2: h->h2
        agg_kernel<<<(NN * 32 + 255) / 256, 256>>>(l, in_is_h2, attl, attr);
    }

    gemm2_kernel<<<1184, 256>>>(t2w, t2b, out, write_emb);
}